// round 16
// baseline (speedup 1.0000x reference)
#include <cuda_runtime.h>
#include <cuda_fp16.h>
#include <cstdint>
#include <math.h>

#define NHEADS 8
#define HC     32
#define HW     4096
#define CDIM   256
#define BDIM   8
#define LDIM   80

// ================= scratch =================
__device__ uint32_t g_wh[2 * 16 * 72 * 128];          // conv weights half2 pairs
__device__ float    g_beta2[CDIM];
__device__ float    g_attn[BDIM * NHEADS * HW];
__device__ uint32_t g_Uh[BDIM * 128 * 8 * 80];        // U half2 pairs
__device__ float    g_c[BDIM * NHEADS * LDIM];
__device__ uint32_t g_imgp[BDIM * 128 * 66 * 72];     // padded half2 image

__device__ __forceinline__ uint32_t pack_h2(float a, float b) {
    __half2 h = __floats2half2_rn(a, b);
    return *reinterpret_cast<uint32_t*>(&h);
}
__device__ __forceinline__ uint32_t smem_u32(const void* p) {
    uint32_t a;
    asm("{ .reg .u64 t; cvta.to.shared.u64 t, %1; cvt.u32.u64 %0, t; }" : "=r"(a) : "l"(p));
    return a;
}
__device__ __forceinline__ void cp_async16(uint32_t dst, const void* src) {
    asm volatile("cp.async.ca.shared.global [%0], [%1], 16;" :: "r"(dst), "l"(src));
}
#define CP_COMMIT() asm volatile("cp.async.commit_group;" ::: "memory")
#define CP_WAIT0()  asm volatile("cp.async.wait_group 0;" ::: "memory")

__device__ __forceinline__ void mma_f16(float* c,
                                        uint32_t a0, uint32_t a1, uint32_t a2, uint32_t a3,
                                        uint32_t b0, uint32_t b1) {
    asm volatile(
        "mma.sync.aligned.m16n8k16.row.col.f32.f16.f16.f32 "
        "{%0,%1,%2,%3}, {%4,%5,%6,%7}, {%8,%9}, {%0,%1,%2,%3};"
        : "+f"(c[0]), "+f"(c[1]), "+f"(c[2]), "+f"(c[3])
        : "r"(a0), "r"(a1), "r"(a2), "r"(a3), "r"(b0), "r"(b1));
}

// ================= K0: merged prep (img 2x4-wide / weights / U) =================
#define IMG_CHUNKS (BDIM * 128 * 66 * 18)     // 1,216,512 uint4 chunks
#define IMG_HALF   (IMG_CHUNKS / 2)           // 608,256
#define IMG_BLOCKS (IMG_HALF / 256)           // 2376 blocks, 2 chunks/thread
#define W_BLOCKS   1152
__global__ void __launch_bounds__(256) prep_misc_kernel(
    const float* __restrict__ img,
    const float* __restrict__ conv_w,
    const float* __restrict__ gamma,
    const float* __restrict__ beta,
    const float* __restrict__ mean,
    const float* __restrict__ var,
    const float* __restrict__ text,
    const float* __restrict__ proj_w,
    const float* __restrict__ proj_b,
    const float* __restrict__ attn_bias) {

    const int bid = blockIdx.x;
    const int tid = threadIdx.x;

    if (bid < IMG_BLOCKS) {
        const int base = bid * 256 + tid;
        #pragma unroll
        for (int k = 0; k < 2; k++) {
            int idx = base + k * IMG_HALF;        // two independent bodies -> MLP x2
            int ch = idx % 18;
            int r  = idx / 18;
            int yp = r % 66;
            int rr = r / 66;
            int p  = rr & 127;
            int b  = rr >> 7;

            uint32_t v0 = 0, v1 = 0, v2 = 0, v3 = 0;
            if (yp >= 1 && yp <= 64) {
                const float* ip0 = img + ((size_t)b * CDIM + 2 * p) * HW + ((yp - 1) << 6);
                const float* ip1 = ip0 + HW;
                float a0[4], a1[4];
                #pragma unroll
                for (int e = 0; e < 4; e++) {
                    int gx = ch * 4 + e - 1;
                    bool ok = (unsigned)gx < 64u;
                    a0[e] = ok ? ip0[gx] : 0.f;
                    a1[e] = ok ? ip1[gx] : 0.f;
                }
                v0 = pack_h2(a0[0], a1[0]);
                v1 = pack_h2(a0[1], a1[1]);
                v2 = pack_h2(a0[2], a1[2]);
                v3 = pack_h2(a0[3], a1[3]);
            }
            *reinterpret_cast<uint4*>(&g_imgp[(size_t)idx * 4]) = make_uint4(v0, v1, v2, v3);
        }
        return;
    }
    if (bid < IMG_BLOCKS + W_BLOCKS) {
        int idx = (bid - IMG_BLOCKS) * 256 + tid;
        if (idx < 2 * 16 * 72 * 128) {
            int co  = idx & 127;
            int r   = idx >> 7;
            int kp  = r & 7;   r >>= 3;
            int tap = r % 9;   r /= 9;
            int cib = r & 15;
            int bN  = r >> 4;
            int ci0 = cib * 16 + 2 * kp;
            int cog = bN * 128 + co;
            float inv = gamma[cog] * rsqrtf(var[cog] + 1e-3f);
            float w0 = conv_w[(cog * CDIM + ci0) * 9 + tap] * inv;
            float w1 = conv_w[(cog * CDIM + ci0 + 1) * 9 + tap] * inv;
            g_wh[idx] = pack_h2(w0, w1);
        }
        if (idx < CDIM) {
            float iv = gamma[idx] * rsqrtf(var[idx] + 1e-3f);
            g_beta2[idx] = beta[idx] - mean[idx] * iv;
        }
        return;
    }

    // ---- U prep: 256 blocks, q = (b<<5) | (h<<2) | z ----
    __shared__ float W_s[HC * 64];
    __shared__ float T_s[LDIM * 33];

    const int q   = bid - IMG_BLOCKS - W_BLOCKS;
    const int b   = q >> 5;
    const int h   = (q >> 2) & 7;
    const int ci0 = (q & 3) * 64;
    const float invs = 0.17677669529663687f;

    for (int i = tid; i < HC * 64; i += 256) {
        int cc = i >> 6, cil = i & 63;
        W_s[i] = proj_w[(h * HC + cc) * CDIM + ci0 + cil];
    }
    for (int i = tid; i < LDIM * HC; i += 256) {
        int n = i >> 5, cc = i & 31;
        T_s[n * 33 + cc] = text[(b * LDIM + n) * CDIM + h * HC + cc];
    }
    __syncthreads();

    for (int i = tid; i < 32 * LDIM; i += 256) {
        int cp = i / LDIM, n = i % LDIM;
        float u0 = 0.f, u1 = 0.f;
        #pragma unroll
        for (int cc = 0; cc < HC; cc++) {
            float tv = T_s[n * 33 + cc];
            u0 += W_s[cc * 64 + 2 * cp]     * tv;
            u1 += W_s[cc * 64 + 2 * cp + 1] * tv;
        }
        int p  = (q & 3) * 32 + cp;
        int kk = p >> 3, kp = p & 7;
        int s  = h * 16 + kk;
        g_Uh[((size_t)(b * 128 + s) * 8 + kp) * 80 + n] = pack_h2(u0 * invs, u1 * invs);
    }
    if ((q & 3) == 0 && tid < LDIM) {
        float cb = 0.f;
        #pragma unroll
        for (int cc = 0; cc < HC; cc++)
            cb += proj_b[h * HC + cc] * T_s[tid * 33 + cc];
        g_c[(b * NHEADS + h) * LDIM + tid] = cb * invs + attn_bias[h];
    }
}

// ================= K1: attn — fp16 mma, 4 heads/CTA, parity max-buffers =================
#define A_PS 152
#define A_RS2 72

__global__ void __launch_bounds__(256, 2) attn_mma_kernel(const float* __restrict__ scale) {

    extern __shared__ __align__(16) uint32_t smA[];
    __shared__ float mxb[2][256];

    const int tid  = threadIdx.x;
    const int wid  = tid >> 5;
    const int lane = tid & 31;
    const int g    = lane >> 2;
    const int t    = lane & 3;

    const int b   = blockIdx.x >> 5;
    const int y0a = (blockIdx.x & 31) << 1;
    const int p0  = y0a << 6;
    const int h0  = blockIdx.y * 4;       // 4 heads per CTA
    const int wm   = (wid & 3) * 32;
    const int wn_i = wid >> 2;
    const int wn   = wn_i * 40;

    const uint32_t sbase = smem_u32(smA);
    const uint32_t* Ug = g_Uh + (size_t)(b * 128 + h0 * 16) * 8 * 80;
    int n0[5];
    #pragma unroll
    for (int nt = 0; nt < 5; nt++) n0[nt] = wn + nt * 8 + g;

    uint32_t ub[2][5][2];
    auto load_u = [&](int s, int buf) {
        const uint32_t* base = Ug + (size_t)s * 640;
        #pragma unroll
        for (int nt = 0; nt < 5; nt++) {
            ub[buf][nt][0] = base[t * 80 + n0[nt]];
            ub[buf][nt][1] = base[(t + 4) * 80 + n0[nt]];
        }
    };
    load_u(0, 0);

    // stage A via cp.async: 128 pairs x 2 padded rows
    {
        const uint32_t* src0 = g_imgp + ((size_t)(b * 128) * 66 + y0a + 1) * 72;
        #pragma unroll
        for (int it = 0; it < 18; it++) {
            int idx = tid + it * 256;
            int p  = idx / 36;
            int r  = idx % 36;
            int ry = r / 18, ch = r % 18;
            cp_async16(sbase + (uint32_t)((p * A_PS + ry * A_RS2 + ch * 4) * 4),
                       src0 + (size_t)p * 66 * 72 + ry * 72 + ch * 4);
        }
        CP_COMMIT();
        CP_WAIT0();
    }
    __syncthreads();

    for (int hh = 0; hh < 4; hh++) {
        const int h = h0 + hh;

        float c[2][5][4];
        #pragma unroll
        for (int mt = 0; mt < 2; mt++)
            #pragma unroll
            for (int nt = 0; nt < 5; nt++)
                #pragma unroll
                for (int i = 0; i < 4; i++) c[mt][nt][i] = 0.f;

        #pragma unroll 4
        for (int kk = 0; kk < 16; kk++) {
            const int s   = hh * 16 + kk;
            const int cur = s & 1;
            if (s + 1 < 64) load_u(s + 1, cur ^ 1);

            uint32_t a[2][4];
            #pragma unroll
            for (int mt = 0; mt < 2; mt++) {
                int m    = wm + mt * 16 + g;
                int prow = m >> 6, pcol = m & 63;
                const uint32_t* p = &smA[(kk * 8 + t) * A_PS + prow * A_RS2 + 1 + pcol];
                a[mt][0] = p[0];
                a[mt][1] = p[8];
                a[mt][2] = p[4 * A_PS];
                a[mt][3] = p[4 * A_PS + 8];
            }
            #pragma unroll
            for (int nt = 0; nt < 5; nt++) {
                mma_f16(c[0][nt], a[0][0], a[0][1], a[0][2], a[0][3],
                        ub[cur][nt][0], ub[cur][nt][1]);
                mma_f16(c[1][nt], a[1][0], a[1][1], a[1][2], a[1][3],
                        ub[cur][nt][0], ub[cur][nt][1]);
            }
        }

        float cn0[5], cn1[5];
        #pragma unroll
        for (int nt = 0; nt < 5; nt++) {
            int nn = wn + nt * 8 + 2 * t;
            cn0[nt] = g_c[(b * NHEADS + h) * LDIM + nn];
            cn1[nt] = g_c[(b * NHEADS + h) * LDIM + nn + 1];
        }
        const int mb = hh & 1;
        #pragma unroll
        for (int mt = 0; mt < 2; mt++) {
            #pragma unroll
            for (int rr = 0; rr < 2; rr++) {
                float mx = -1e30f;
                #pragma unroll
                for (int nt = 0; nt < 5; nt++) {
                    mx = fmaxf(mx, fmaxf(c[mt][nt][rr * 2] + cn0[nt],
                                         c[mt][nt][rr * 2 + 1] + cn1[nt]));
                }
                mx = fmaxf(mx, __shfl_xor_sync(0xFFFFFFFF, mx, 1));
                mx = fmaxf(mx, __shfl_xor_sync(0xFFFFFFFF, mx, 2));
                if (t == 0)
                    mxb[mb][wn_i * 128 + wm + mt * 16 + rr * 8 + g] = mx;
            }
        }
        __syncthreads();
        if (tid < 128) {
            float z = fmaxf(mxb[mb][tid], mxb[mb][128 + tid]);
            float a = (1.0f / (1.0f + expf(-z))) * scale[h];
            g_attn[((b * NHEADS + h) << 12) + p0 + tid] = a;
        }
        // parity buffer: next head writes the other mxb; one barrier per head suffices
    }
}

// ================= K2: conv — single-barrier double-buffered pipeline (proven) =================
#define RAW_RS  72
#define RAW_PS  296
#define WCO     136
#define CV_RAW0 0
#define CV_RAW1 2368
#define CV_WS0  4736
#define CV_WS1  (4736 + 9792)
#define CV_TOT  (4736 + 2 * 9792)

__global__ void __launch_bounds__(256, 2) conv_mma_kernel(float* __restrict__ out) {

    extern __shared__ __align__(16) uint32_t sm[];
    __shared__ float b2s[128];
    const uint32_t sbase = smem_u32(sm);

    const int tid  = threadIdx.x;
    const int wid  = tid >> 5;
    const int lane = tid & 31;
    const int g    = lane >> 2;
    const int t    = lane & 3;

    const int bM = blockIdx.x;
    const int bN = blockIdx.y;
    const int b  = bM >> 5;
    const int y0 = (bM & 31) << 1;
    const int wm = (wid & 3) * 32;
    const int wn = (wid >> 2) * 64;

    const uint32_t* imgp = g_imgp + (size_t)(b * 128) * 66 * 72;
    const uint32_t* wsrc = g_wh + (size_t)bN * 16 * 9216;

    if (tid < 128) b2s[tid] = g_beta2[bN * 128 + tid];

    auto stage_all = [&](int cib, int buf) {
        const uint32_t rdst = sbase + (uint32_t)((buf ? CV_RAW1 : CV_RAW0) * 4);
        const uint32_t* src0 = imgp + ((size_t)(cib * 8) * 66 + y0) * 72;
        #pragma unroll
        for (int it = 0; it < 3; it++) {
            int idx = tid + it * 256;
            if (idx < 576) {
                int p  = idx / 72;
                int r  = idx % 72;
                int ry = r / 18, ch = r % 18;
                cp_async16(rdst + (uint32_t)((p * RAW_PS + ry * RAW_RS + ch * 4) * 4),
                           src0 + (size_t)p * 66 * 72 + ry * 72 + ch * 4);
            }
        }
        const uint32_t wdst = sbase + (uint32_t)((buf ? CV_WS1 : CV_WS0) * 4);
        #pragma unroll
        for (int it = 0; it < 9; it++) {
            int idx = tid + it * 256;
            int row = idx >> 5;
            int ch  = idx & 31;
            cp_async16(wdst + (uint32_t)((row * WCO + ch * 4) * 4),
                       wsrc + (size_t)cib * 9216 + (idx << 2));
        }
        CP_COMMIT();
    };

    float c[2][8][4];
    #pragma unroll
    for (int mt = 0; mt < 2; mt++)
        #pragma unroll
        for (int nt = 0; nt < 8; nt++)
            #pragma unroll
            for (int i = 0; i < 4; i++) c[mt][nt][i] = 0.f;

    stage_all(0, 0);

    for (int cib = 0; cib < 16; cib++) {
        const int cur = cib & 1;
        CP_WAIT0();
        __syncthreads();
        if (cib + 1 < 16) stage_all(cib + 1, cur ^ 1);

        const uint32_t* raw = sm + (cur ? CV_RAW1 : CV_RAW0);
        const uint32_t* wsm = sm + (cur ? CV_WS1  : CV_WS0);

        #pragma unroll
        for (int tap = 0; tap < 9; tap++) {
            const int ky = tap / 3, kx = tap % 3;

            uint32_t a[2][4];
            #pragma unroll
            for (int mt = 0; mt < 2; mt++) {
                int m    = wm + mt * 16 + g;
                int prow = m >> 6, pcol = m & 63;
                const uint32_t* p = &raw[t * RAW_PS + (prow + ky) * RAW_RS + pcol + kx];
                a[mt][0] = p[0];
                a[mt][1] = p[8];
                a[mt][2] = p[4 * RAW_PS];
                a[mt][3] = p[4 * RAW_PS + 8];
            }
            const uint32_t* w0 = &wsm[(tap * 8 + t) * WCO + wn + g];
            const uint32_t* w1 = &wsm[(tap * 8 + t + 4) * WCO + wn + g];
            #pragma unroll
            for (int nt = 0; nt < 8; nt++) {
                uint32_t b0 = w0[nt * 8];
                uint32_t b1 = w1[nt * 8];
                mma_f16(c[0][nt], a[0][0], a[0][1], a[0][2], a[0][3], b0, b1);
                mma_f16(c[1][nt], a[1][0], a[1][1], a[1][2], a[1][3], b0, b1);
            }
        }
    }

    #pragma unroll
    for (int mt = 0; mt < 2; mt++) {
        #pragma unroll
        for (int rr = 0; rr < 2; rr++) {
            int m   = wm + mt * 16 + g + rr * 8;
            int pix = (y0 << 6) + m;
            #pragma unroll
            for (int nt = 0; nt < 8; nt++) {
                int co = bN * 128 + wn + nt * 8 + 2 * t;
                float gate = g_attn[((b * NHEADS + (co >> 5)) << 12) + pix];
                float v0 = c[mt][nt][rr * 2 + 0] + b2s[wn + nt * 8 + 2 * t];
                float v1 = c[mt][nt][rr * 2 + 1] + b2s[wn + nt * 8 + 2 * t + 1];
                out[(((size_t)b * CDIM + co) << 12) + pix]     = v0 * gate;
                out[(((size_t)b * CDIM + co + 1) << 12) + pix] = v1 * gate;
            }
        }
    }
}

// ================= launch =================
extern "C" void kernel_launch(void* const* d_in, const int* in_sizes, int n_in,
                              void* d_out, int out_size) {
    const float* img_feat   = (const float*)d_in[0];
    const float* text_feats = (const float*)d_in[1];
    const float* proj_w     = (const float*)d_in[2];
    const float* proj_b     = (const float*)d_in[3];
    const float* attn_bias  = (const float*)d_in[4];
    const float* scale      = (const float*)d_in[5];
    const float* conv_w     = (const float*)d_in[6];
    const float* bn_gamma   = (const float*)d_in[7];
    const float* bn_beta    = (const float*)d_in[8];
    const float* bn_mean    = (const float*)d_in[9];
    const float* bn_var     = (const float*)d_in[10];
    float* out = (float*)d_out;

    static int attr_set = 0;
    if (!attr_set) {
        cudaFuncSetAttribute(attn_mma_kernel,
                             cudaFuncAttributeMaxDynamicSharedMemorySize, 128 * A_PS * 4);
        cudaFuncSetAttribute(conv_mma_kernel,
                             cudaFuncAttributeMaxDynamicSharedMemorySize, CV_TOT * 4);
        attr_set = 1;
    }

    prep_misc_kernel<<<IMG_BLOCKS + W_BLOCKS + 256, 256>>>(
        img_feat, conv_w, bn_gamma, bn_beta, bn_mean, bn_var,
        text_feats, proj_w, proj_b, attn_bias);

    dim3 g1(BDIM * 32, 2);
    attn_mma_kernel<<<g1, 256, 128 * A_PS * 4>>>(scale);

    dim3 g2(256, 2);
    conv_mma_kernel<<<g2, 256, CV_TOT * 4>>>(out);
}

// round 17
// speedup vs baseline: 1.0139x; 1.0139x over previous
#include <cuda_runtime.h>
#include <cuda_fp16.h>
#include <cstdint>
#include <math.h>

#define NHEADS 8
#define HC     32
#define HW     4096
#define CDIM   256
#define BDIM   8
#define LDIM   80

// ================= scratch =================
__device__ uint32_t g_wh[2 * 16 * 72 * 128];          // conv weights half2 pairs
__device__ float    g_beta2[CDIM];
__device__ float    g_attn[BDIM * NHEADS * HW];
__device__ uint32_t g_Uh[BDIM * 128 * 8 * 80];        // U half2 pairs
__device__ float    g_c[BDIM * NHEADS * LDIM];
__device__ uint32_t g_imgp[BDIM * 128 * 66 * 72];     // padded half2 image

__device__ __forceinline__ uint32_t pack_h2(float a, float b) {
    __half2 h = __floats2half2_rn(a, b);
    return *reinterpret_cast<uint32_t*>(&h);
}
__device__ __forceinline__ uint32_t smem_u32(const void* p) {
    uint32_t a;
    asm("{ .reg .u64 t; cvta.to.shared.u64 t, %1; cvt.u32.u64 %0, t; }" : "=r"(a) : "l"(p));
    return a;
}
__device__ __forceinline__ void cp_async16(uint32_t dst, const void* src) {
    asm volatile("cp.async.ca.shared.global [%0], [%1], 16;" :: "r"(dst), "l"(src));
}
#define CP_COMMIT() asm volatile("cp.async.commit_group;" ::: "memory")
#define CP_WAIT0()  asm volatile("cp.async.wait_group 0;" ::: "memory")

__device__ __forceinline__ void mma_f16(float* c,
                                        uint32_t a0, uint32_t a1, uint32_t a2, uint32_t a3,
                                        uint32_t b0, uint32_t b1) {
    asm volatile(
        "mma.sync.aligned.m16n8k16.row.col.f32.f16.f16.f32 "
        "{%0,%1,%2,%3}, {%4,%5,%6,%7}, {%8,%9}, {%0,%1,%2,%3};"
        : "+f"(c[0]), "+f"(c[1]), "+f"(c[2]), "+f"(c[3])
        : "r"(a0), "r"(a1), "r"(a2), "r"(a3), "r"(b0), "r"(b1));
}

// ================= K0: merged prep (img 4-wide / weights / U) =================
#define IMG_BLOCKS 4752      // (8*128*66*18)/256 threads, 1 uint4 each
#define W_BLOCKS   1152
__global__ void __launch_bounds__(256) prep_misc_kernel(
    const float* __restrict__ img,
    const float* __restrict__ conv_w,
    const float* __restrict__ gamma,
    const float* __restrict__ beta,
    const float* __restrict__ mean,
    const float* __restrict__ var,
    const float* __restrict__ text,
    const float* __restrict__ proj_w,
    const float* __restrict__ proj_b,
    const float* __restrict__ attn_bias) {

    const int bid = blockIdx.x;
    const int tid = threadIdx.x;

    if (bid < IMG_BLOCKS) {
        int idx = bid * 256 + tid;            // over [b][p][yp][ch], ch = xp/4
        int ch = idx % 18;
        int r  = idx / 18;
        int yp = r % 66;
        int rr = r / 66;
        int p  = rr & 127;
        int b  = rr >> 7;

        uint32_t v0 = 0, v1 = 0, v2 = 0, v3 = 0;
        if (yp >= 1 && yp <= 64) {
            const float* ip0 = img + ((size_t)b * CDIM + 2 * p) * HW + ((yp - 1) << 6);
            const float* ip1 = ip0 + HW;
            float a0[4], a1[4];
            #pragma unroll
            for (int e = 0; e < 4; e++) {
                int gx = ch * 4 + e - 1;
                bool ok = (unsigned)gx < 64u;
                a0[e] = ok ? ip0[gx] : 0.f;
                a1[e] = ok ? ip1[gx] : 0.f;
            }
            v0 = pack_h2(a0[0], a1[0]);
            v1 = pack_h2(a0[1], a1[1]);
            v2 = pack_h2(a0[2], a1[2]);
            v3 = pack_h2(a0[3], a1[3]);
        }
        *reinterpret_cast<uint4*>(&g_imgp[(size_t)idx * 4]) = make_uint4(v0, v1, v2, v3);
        return;
    }
    if (bid < IMG_BLOCKS + W_BLOCKS) {
        int idx = (bid - IMG_BLOCKS) * 256 + tid;
        if (idx < 2 * 16 * 72 * 128) {
            int co  = idx & 127;
            int r   = idx >> 7;
            int kp  = r & 7;   r >>= 3;
            int tap = r % 9;   r /= 9;
            int cib = r & 15;
            int bN  = r >> 4;
            int ci0 = cib * 16 + 2 * kp;
            int cog = bN * 128 + co;
            float inv = gamma[cog] * rsqrtf(var[cog] + 1e-3f);
            float w0 = conv_w[(cog * CDIM + ci0) * 9 + tap] * inv;
            float w1 = conv_w[(cog * CDIM + ci0 + 1) * 9 + tap] * inv;
            g_wh[idx] = pack_h2(w0, w1);
        }
        if (idx < CDIM) {
            float iv = gamma[idx] * rsqrtf(var[idx] + 1e-3f);
            g_beta2[idx] = beta[idx] - mean[idx] * iv;
        }
        return;
    }

    // ---- U prep: 256 blocks, q = (b<<5) | (h<<2) | z ----
    __shared__ float W_s[HC * 64];
    __shared__ float T_s[LDIM * 33];

    const int q   = bid - IMG_BLOCKS - W_BLOCKS;
    const int b   = q >> 5;
    const int h   = (q >> 2) & 7;
    const int ci0 = (q & 3) * 64;
    const float invs = 0.17677669529663687f;

    for (int i = tid; i < HC * 64; i += 256) {
        int cc = i >> 6, cil = i & 63;
        W_s[i] = proj_w[(h * HC + cc) * CDIM + ci0 + cil];
    }
    for (int i = tid; i < LDIM * HC; i += 256) {
        int n = i >> 5, cc = i & 31;
        T_s[n * 33 + cc] = text[(b * LDIM + n) * CDIM + h * HC + cc];
    }
    __syncthreads();

    for (int i = tid; i < 32 * LDIM; i += 256) {
        int cp = i / LDIM, n = i % LDIM;
        float u0 = 0.f, u1 = 0.f;
        #pragma unroll
        for (int cc = 0; cc < HC; cc++) {
            float tv = T_s[n * 33 + cc];
            u0 += W_s[cc * 64 + 2 * cp]     * tv;
            u1 += W_s[cc * 64 + 2 * cp + 1] * tv;
        }
        int p  = (q & 3) * 32 + cp;
        int kk = p >> 3, kp = p & 7;
        int s  = h * 16 + kk;
        g_Uh[((size_t)(b * 128 + s) * 8 + kp) * 80 + n] = pack_h2(u0 * invs, u1 * invs);
    }
    if ((q & 3) == 0 && tid < LDIM) {
        float cb = 0.f;
        #pragma unroll
        for (int cc = 0; cc < HC; cc++)
            cb += proj_b[h * HC + cc] * T_s[tid * 33 + cc];
        g_c[(b * NHEADS + h) * LDIM + tid] = cb * invs + attn_bias[h];
    }
}

// ================= K1: attn — fp16 mma, 4 heads/CTA, parity max-buffers =================
#define A_PS 152
#define A_RS2 72

__global__ void __launch_bounds__(256, 2) attn_mma_kernel(const float* __restrict__ scale) {

    extern __shared__ __align__(16) uint32_t smA[];
    __shared__ float mxb[2][256];

    const int tid  = threadIdx.x;
    const int wid  = tid >> 5;
    const int lane = tid & 31;
    const int g    = lane >> 2;
    const int t    = lane & 3;

    const int b   = blockIdx.x >> 5;
    const int y0a = (blockIdx.x & 31) << 1;
    const int p0  = y0a << 6;
    const int h0  = blockIdx.y * 4;       // 4 heads per CTA
    const int wm   = (wid & 3) * 32;
    const int wn_i = wid >> 2;
    const int wn   = wn_i * 40;

    const uint32_t sbase = smem_u32(smA);
    const uint32_t* Ug = g_Uh + (size_t)(b * 128 + h0 * 16) * 8 * 80;
    int n0[5];
    #pragma unroll
    for (int nt = 0; nt < 5; nt++) n0[nt] = wn + nt * 8 + g;

    uint32_t ub[2][5][2];
    auto load_u = [&](int s, int buf) {
        const uint32_t* base = Ug + (size_t)s * 640;
        #pragma unroll
        for (int nt = 0; nt < 5; nt++) {
            ub[buf][nt][0] = base[t * 80 + n0[nt]];
            ub[buf][nt][1] = base[(t + 4) * 80 + n0[nt]];
        }
    };
    load_u(0, 0);

    // stage A via cp.async: 128 pairs x 2 padded rows
    {
        const uint32_t* src0 = g_imgp + ((size_t)(b * 128) * 66 + y0a + 1) * 72;
        #pragma unroll
        for (int it = 0; it < 18; it++) {
            int idx = tid + it * 256;
            int p  = idx / 36;
            int r  = idx % 36;
            int ry = r / 18, ch = r % 18;
            cp_async16(sbase + (uint32_t)((p * A_PS + ry * A_RS2 + ch * 4) * 4),
                       src0 + (size_t)p * 66 * 72 + ry * 72 + ch * 4);
        }
        CP_COMMIT();
        CP_WAIT0();
    }
    __syncthreads();

    for (int hh = 0; hh < 4; hh++) {
        const int h = h0 + hh;

        float c[2][5][4];
        #pragma unroll
        for (int mt = 0; mt < 2; mt++)
            #pragma unroll
            for (int nt = 0; nt < 5; nt++)
                #pragma unroll
                for (int i = 0; i < 4; i++) c[mt][nt][i] = 0.f;

        #pragma unroll 4
        for (int kk = 0; kk < 16; kk++) {
            const int s   = hh * 16 + kk;
            const int cur = s & 1;
            if (s + 1 < 64) load_u(s + 1, cur ^ 1);

            uint32_t a[2][4];
            #pragma unroll
            for (int mt = 0; mt < 2; mt++) {
                int m    = wm + mt * 16 + g;
                int prow = m >> 6, pcol = m & 63;
                const uint32_t* p = &smA[(kk * 8 + t) * A_PS + prow * A_RS2 + 1 + pcol];
                a[mt][0] = p[0];
                a[mt][1] = p[8];
                a[mt][2] = p[4 * A_PS];
                a[mt][3] = p[4 * A_PS + 8];
            }
            #pragma unroll
            for (int nt = 0; nt < 5; nt++) {
                mma_f16(c[0][nt], a[0][0], a[0][1], a[0][2], a[0][3],
                        ub[cur][nt][0], ub[cur][nt][1]);
                mma_f16(c[1][nt], a[1][0], a[1][1], a[1][2], a[1][3],
                        ub[cur][nt][0], ub[cur][nt][1]);
            }
        }

        float cn0[5], cn1[5];
        #pragma unroll
        for (int nt = 0; nt < 5; nt++) {
            int nn = wn + nt * 8 + 2 * t;
            cn0[nt] = g_c[(b * NHEADS + h) * LDIM + nn];
            cn1[nt] = g_c[(b * NHEADS + h) * LDIM + nn + 1];
        }
        const int mb = hh & 1;
        #pragma unroll
        for (int mt = 0; mt < 2; mt++) {
            #pragma unroll
            for (int rr = 0; rr < 2; rr++) {
                float mx = -1e30f;
                #pragma unroll
                for (int nt = 0; nt < 5; nt++) {
                    mx = fmaxf(mx, fmaxf(c[mt][nt][rr * 2] + cn0[nt],
                                         c[mt][nt][rr * 2 + 1] + cn1[nt]));
                }
                mx = fmaxf(mx, __shfl_xor_sync(0xFFFFFFFF, mx, 1));
                mx = fmaxf(mx, __shfl_xor_sync(0xFFFFFFFF, mx, 2));
                if (t == 0)
                    mxb[mb][wn_i * 128 + wm + mt * 16 + rr * 8 + g] = mx;
            }
        }
        __syncthreads();
        if (tid < 128) {
            float z = fmaxf(mxb[mb][tid], mxb[mb][128 + tid]);
            float a = (1.0f / (1.0f + expf(-z))) * scale[h];
            g_attn[((b * NHEADS + h) << 12) + p0 + tid] = a;
        }
        // parity buffer: next head writes the other mxb; one barrier per head suffices
    }
}

// ================= K2: conv — pipeline unchanged, epilogue WITHOUT gate =================
#define RAW_RS  72
#define RAW_PS  296
#define WCO     136
#define CV_RAW0 0
#define CV_RAW1 2368
#define CV_WS0  4736
#define CV_WS1  (4736 + 9792)
#define CV_TOT  (4736 + 2 * 9792)

__global__ void __launch_bounds__(256, 2) conv_mma_kernel(float* __restrict__ out) {

    extern __shared__ __align__(16) uint32_t sm[];
    __shared__ float b2s[128];
    const uint32_t sbase = smem_u32(sm);

    const int tid  = threadIdx.x;
    const int wid  = tid >> 5;
    const int lane = tid & 31;
    const int g    = lane >> 2;
    const int t    = lane & 3;

    const int bM = blockIdx.x;
    const int bN = blockIdx.y;
    const int b  = bM >> 5;
    const int y0 = (bM & 31) << 1;
    const int wm = (wid & 3) * 32;
    const int wn = (wid >> 2) * 64;

    const uint32_t* imgp = g_imgp + (size_t)(b * 128) * 66 * 72;
    const uint32_t* wsrc = g_wh + (size_t)bN * 16 * 9216;

    if (tid < 128) b2s[tid] = g_beta2[bN * 128 + tid];

    auto stage_all = [&](int cib, int buf) {
        const uint32_t rdst = sbase + (uint32_t)((buf ? CV_RAW1 : CV_RAW0) * 4);
        const uint32_t* src0 = imgp + ((size_t)(cib * 8) * 66 + y0) * 72;
        #pragma unroll
        for (int it = 0; it < 3; it++) {
            int idx = tid + it * 256;
            if (idx < 576) {
                int p  = idx / 72;
                int r  = idx % 72;
                int ry = r / 18, ch = r % 18;
                cp_async16(rdst + (uint32_t)((p * RAW_PS + ry * RAW_RS + ch * 4) * 4),
                           src0 + (size_t)p * 66 * 72 + ry * 72 + ch * 4);
            }
        }
        const uint32_t wdst = sbase + (uint32_t)((buf ? CV_WS1 : CV_WS0) * 4);
        #pragma unroll
        for (int it = 0; it < 9; it++) {
            int idx = tid + it * 256;
            int row = idx >> 5;
            int ch  = idx & 31;
            cp_async16(wdst + (uint32_t)((row * WCO + ch * 4) * 4),
                       wsrc + (size_t)cib * 9216 + (idx << 2));
        }
        CP_COMMIT();
    };

    float c[2][8][4];
    #pragma unroll
    for (int mt = 0; mt < 2; mt++)
        #pragma unroll
        for (int nt = 0; nt < 8; nt++)
            #pragma unroll
            for (int i = 0; i < 4; i++) c[mt][nt][i] = 0.f;

    stage_all(0, 0);

    for (int cib = 0; cib < 16; cib++) {
        const int cur = cib & 1;
        CP_WAIT0();
        __syncthreads();
        if (cib + 1 < 16) stage_all(cib + 1, cur ^ 1);

        const uint32_t* raw = sm + (cur ? CV_RAW1 : CV_RAW0);
        const uint32_t* wsm = sm + (cur ? CV_WS1  : CV_WS0);

        #pragma unroll
        for (int tap = 0; tap < 9; tap++) {
            const int ky = tap / 3, kx = tap % 3;

            uint32_t a[2][4];
            #pragma unroll
            for (int mt = 0; mt < 2; mt++) {
                int m    = wm + mt * 16 + g;
                int prow = m >> 6, pcol = m & 63;
                const uint32_t* p = &raw[t * RAW_PS + (prow + ky) * RAW_RS + pcol + kx];
                a[mt][0] = p[0];
                a[mt][1] = p[8];
                a[mt][2] = p[4 * RAW_PS];
                a[mt][3] = p[4 * RAW_PS + 8];
            }
            const uint32_t* w0 = &wsm[(tap * 8 + t) * WCO + wn + g];
            const uint32_t* w1 = &wsm[(tap * 8 + t + 4) * WCO + wn + g];
            #pragma unroll
            for (int nt = 0; nt < 8; nt++) {
                uint32_t b0 = w0[nt * 8];
                uint32_t b1 = w1[nt * 8];
                mma_f16(c[0][nt], a[0][0], a[0][1], a[0][2], a[0][3], b0, b1);
                mma_f16(c[1][nt], a[1][0], a[1][1], a[1][2], a[1][3], b0, b1);
            }
        }
    }

    // epilogue: +beta2, store (gate applied later by gate_kernel)
    #pragma unroll
    for (int mt = 0; mt < 2; mt++) {
        #pragma unroll
        for (int rr = 0; rr < 2; rr++) {
            int m   = wm + mt * 16 + g + rr * 8;
            int pix = (y0 << 6) + m;
            #pragma unroll
            for (int nt = 0; nt < 8; nt++) {
                int co = bN * 128 + wn + nt * 8 + 2 * t;
                float v0 = c[mt][nt][rr * 2 + 0] + b2s[wn + nt * 8 + 2 * t];
                float v1 = c[mt][nt][rr * 2 + 1] + b2s[wn + nt * 8 + 2 * t + 1];
                out[(((size_t)b * CDIM + co) << 12) + pix]     = v0;
                out[(((size_t)b * CDIM + co + 1) << 12) + pix] = v1;
            }
        }
    }
}

// ================= K3: gate — out *= attn (float4 streaming) =================
__global__ void __launch_bounds__(256) gate_kernel(float* __restrict__ out) {
    int idx = blockIdx.x * 256 + threadIdx.x;   // float4 index, 2,097,152 total
    int pix4 = idx & 1023;
    int r    = idx >> 10;
    int co   = r & 255;
    int b    = r >> 8;

    float4 v = reinterpret_cast<float4*>(out)[idx];
    const float4 a = *reinterpret_cast<const float4*>(
        &g_attn[(((b << 3) + (co >> 5)) << 12) + (pix4 << 2)]);
    v.x *= a.x; v.y *= a.y; v.z *= a.z; v.w *= a.w;
    reinterpret_cast<float4*>(out)[idx] = v;
}

// ================= launch =================
extern "C" void kernel_launch(void* const* d_in, const int* in_sizes, int n_in,
                              void* d_out, int out_size) {
    const float* img_feat   = (const float*)d_in[0];
    const float* text_feats = (const float*)d_in[1];
    const float* proj_w     = (const float*)d_in[2];
    const float* proj_b     = (const float*)d_in[3];
    const float* attn_bias  = (const float*)d_in[4];
    const float* scale      = (const float*)d_in[5];
    const float* conv_w     = (const float*)d_in[6];
    const float* bn_gamma   = (const float*)d_in[7];
    const float* bn_beta    = (const float*)d_in[8];
    const float* bn_mean    = (const float*)d_in[9];
    const float* bn_var     = (const float*)d_in[10];
    float* out = (float*)d_out;

    static cudaStream_t s1 = nullptr;
    static cudaEvent_t  e1 = nullptr, e2 = nullptr;
    if (!s1) {
        cudaStreamCreateWithFlags(&s1, cudaStreamNonBlocking);
        cudaEventCreateWithFlags(&e1, cudaEventDisableTiming);
        cudaEventCreateWithFlags(&e2, cudaEventDisableTiming);
        cudaFuncSetAttribute(attn_mma_kernel,
                             cudaFuncAttributeMaxDynamicSharedMemorySize, 128 * A_PS * 4);
        cudaFuncSetAttribute(conv_mma_kernel,
                             cudaFuncAttributeMaxDynamicSharedMemorySize, CV_TOT * 4);
    }

    prep_misc_kernel<<<IMG_BLOCKS + W_BLOCKS + 256, 256>>>(
        img_feat, conv_w, bn_gamma, bn_beta, bn_mean, bn_var,
        text_feats, proj_w, proj_b, attn_bias);

    // fork: attn on side stream, conv on main stream
    cudaEventRecord(e1, 0);
    cudaStreamWaitEvent(s1, e1, 0);

    dim3 g1(BDIM * 32, 2);
    attn_mma_kernel<<<g1, 256, 128 * A_PS * 4, s1>>>(scale);
    cudaEventRecord(e2, s1);

    dim3 g2(256, 2);
    conv_mma_kernel<<<g2, 256, CV_TOT * 4>>>(out);

    // join: gate needs both conv (main) and attn (s1)
    cudaStreamWaitEvent(0, e2, 0);
    gate_kernel<<<8192, 256>>>(out);
}